// round 15
// baseline (speedup 1.0000x reference)
#include <cuda_runtime.h>
#include <cuda_bf16.h>
#include <cuda_fp16.h>
#include <cstdint>

// ---------------------------------------------------------------------------
// Problem constants
// ---------------------------------------------------------------------------
#define BT    2048      // B*T
#define NB    24        // bands
#define D     512       // DIM
#define E2    1024      // 2*DIM
#define OUTW  2016      // sum(DIM_INPUTS)
#define W1C   4032      // 2*OUTW
#define LDA   72        // stage2 smem row stride (64 data + 8 pad) f16
#define LDA2  136       // stage1 smem row stride (128 data + 8 pad) f16

// Scratch globals (all f16). x and h are BAND-MAJOR: [n][row][k].
__device__ __half g_x16[(size_t)NB * BT * D];  // x    f16 [n][row][k]
__device__ __half g_w16[(size_t)NB * E2 * D];  // W0^T f16 [n][e][k]
__device__ __half g_h16[(size_t)NB * BT * D];  // h    f16 [n][row][k]
__device__ __half g_v16[(size_t)W1C * D];      // W1^T f16 [e][k]

// ---------------------------------------------------------------------------
// Helpers
// ---------------------------------------------------------------------------
__device__ __forceinline__ uint32_t smem_u32(const void* p) {
    uint32_t a;
    asm("{ .reg .u64 t; cvta.to.shared.u64 t, %1; cvt.u32.u64 %0, t; }"
        : "=r"(a) : "l"(p));
    return a;
}
__device__ __forceinline__ void cp16(uint32_t dst, const void* src) {
    asm volatile("cp.async.cg.shared.global [%0], [%1], 16;"
                 :: "r"(dst), "l"(src));
}
__device__ __forceinline__ void cp16z(uint32_t dst, const void* src, bool valid) {
    int sz = valid ? 16 : 0;
    asm volatile("cp.async.cg.shared.global [%0], [%1], 16, %2;"
                 :: "r"(dst), "l"(src), "r"(sz));
}
__device__ __forceinline__ void cp_commit() {
    asm volatile("cp.async.commit_group;");
}
__device__ __forceinline__ void cp_wait1() {
    asm volatile("cp.async.wait_group 1;");
}
__device__ __forceinline__ void cp_wait0() {
    asm volatile("cp.async.wait_group 0;");
}
__device__ __forceinline__ void ldm_x4(uint32_t* r, uint32_t addr) {
    asm volatile("ldmatrix.sync.aligned.m8n8.x4.shared.b16 {%0,%1,%2,%3}, [%4];"
        : "=r"(r[0]), "=r"(r[1]), "=r"(r[2]), "=r"(r[3]) : "r"(addr));
}
__device__ __forceinline__ void mma_f16(float* c, const uint32_t* a,
                                        const uint32_t* b) {
    asm volatile(
        "mma.sync.aligned.m16n8k16.row.col.f32.f16.f16.f32 "
        "{%0,%1,%2,%3}, {%4,%5,%6,%7}, {%8,%9}, {%0,%1,%2,%3};"
        : "+f"(c[0]), "+f"(c[1]), "+f"(c[2]), "+f"(c[3])
        : "r"(a[0]), "r"(a[1]), "r"(a[2]), "r"(a[3]), "r"(b[0]), "r"(b[1]));
}
__device__ __forceinline__ float fast_tanh(float x) {
    float r; asm("tanh.approx.f32 %0, %1;" : "=f"(r) : "f"(x)); return r;
}
__device__ __forceinline__ float glu(float a, float g) {
    return fast_tanh(a) * __fdividef(1.0f, 1.0f + __expf(-g));
}
__device__ __forceinline__ uint32_t pack_h2(float lo, float hi) {
    __half2 t = __floats2half2_rn(lo, hi);
    return *(uint32_t*)&t;
}

// ---------------------------------------------------------------------------
// Prologue 1: x f32 [row][n][k] -> g_x16 f16 [n][row][k]
// ---------------------------------------------------------------------------
__global__ __launch_bounds__(256) void cvt_x16_kernel(const float* __restrict__ x)
{
    const size_t total8 = (size_t)BT * NB * D / 8;
    const float4* in = (const float4*)x;
    for (size_t i = blockIdx.x * blockDim.x + threadIdx.x; i < total8;
         i += (size_t)gridDim.x * blockDim.x) {
        const size_t e0  = i * 8;
        const int    row = (int)(e0 / (NB * D));
        const int    rem = (int)(e0 % (NB * D));
        const int    n   = rem / D;
        const int    k   = rem % D;

        float4 v0 = in[2 * i];
        float4 v1 = in[2 * i + 1];
        uint4 o;
        o.x = pack_h2(v0.x, v0.y);
        o.y = pack_h2(v0.z, v0.w);
        o.z = pack_h2(v1.x, v1.y);
        o.w = pack_h2(v1.z, v1.w);
        *(uint4*)(g_x16 + ((size_t)n * BT + row) * D + k) = o;
    }
}

// ---------------------------------------------------------------------------
// Prologue 2: W0 [n][k][e] f32 -> g_w16 [n][e][k] f16 (transpose)
// ---------------------------------------------------------------------------
__global__ __launch_bounds__(256) void cvt_w0_kernel(const float* __restrict__ W0)
{
    __shared__ float t[32][33];
    const int k0 = blockIdx.x * 32;
    const int e0 = blockIdx.y * 32;
    const int n  = blockIdx.z;
    const int tx = threadIdx.x, ty = threadIdx.y;

    #pragma unroll
    for (int i = 0; i < 32; i += 8)
        t[ty + i][tx] = W0[((size_t)n * D + k0 + ty + i) * E2 + e0 + tx];
    __syncthreads();
    #pragma unroll
    for (int i = 0; i < 32; i += 8) {
        float v = t[tx][ty + i];
        g_w16[((size_t)n * E2 + e0 + ty + i) * D + k0 + tx] = __float2half_rn(v);
    }
}

// ---------------------------------------------------------------------------
// Prologue 3: W1 [k][e] f32 -> g_v16 [e][k] f16 (transpose)
// ---------------------------------------------------------------------------
__global__ __launch_bounds__(256) void cvt_w1_kernel(const float* __restrict__ W1)
{
    __shared__ float t[32][33];
    const int k0 = blockIdx.x * 32;
    const int e0 = blockIdx.y * 32;
    const int tx = threadIdx.x, ty = threadIdx.y;

    #pragma unroll
    for (int i = 0; i < 32; i += 8)
        t[ty + i][tx] = W1[(size_t)(k0 + ty + i) * W1C + e0 + tx];
    __syncthreads();
    #pragma unroll
    for (int i = 0; i < 32; i += 8) {
        float v = t[tx][ty + i];
        g_v16[(size_t)(e0 + ty + i) * D + k0 + tx] = __float2half_rn(v);
    }
}

// ---------------------------------------------------------------------------
// Stage 1 (fp16, K-chunk 128, 4 phases): z = x @ W0[n] + b0[n]; h = GLU(z)
// Grid: (16, 4, 24). Block 512 = 16 warps (4 m x 4 n), 1 CTA/SM.
// CTA tile: M=128, GEMM N=256 (128 a + 128 gate); warp tile 32x64.
// K chunk 128 -> 4 chunks. A/B double-buffered (2 stages each, 204 KB smem),
// schedule: wait0 -> sync -> issue(c+1) -> compute(c). ONE sync per chunk,
// 4 barrier phases total (was 8) — R15: phase-overhead reduction.
// ---------------------------------------------------------------------------
#define S1_AMAT   (128 * LDA2)              // 17408 elems per A stage
#define S1_BMAT   (256 * LDA2)              // 34816 elems per B stage
#define S1_BBASE  (2 * S1_AMAT)
#define S1_SMEM   ((2 * S1_AMAT + 2 * S1_BMAT) * 2)   // 208896 B

__global__ __launch_bounds__(512, 1) void stage1_mma_kernel(
    const float* __restrict__ b0)
{
    extern __shared__ __half smem[];

    const int tid = threadIdx.x;
    const int wid = tid >> 5;
    const int lane = tid & 31;
    const int warp_m = wid & 3;         // 4 m-warps
    const int warp_n = wid >> 2;        // 4 n-warps
    const int row0 = blockIdx.x * 128;
    const int ja   = blockIdx.y * 128;
    const int n    = blockIdx.z;

    float acc[2][8][4];
    #pragma unroll
    for (int mi = 0; mi < 2; mi++)
        #pragma unroll
        for (int j = 0; j < 8; j++)
            #pragma unroll
            for (int r = 0; r < 4; r++) acc[mi][j][r] = 0.0f;

    const uint32_t smb = smem_u32(smem);

    const int aRow = warp_m * 32 + (lane & 15);
    const int aK   = (lane >> 4) * 8;
    const int bN   = (lane & 7) + ((lane >> 4) << 3);
    const int bK   = ((lane >> 3) & 1) << 3;

    // A cp.async: 128 rows x 16 segs = 2048; 512 thr -> row tid>>2,
    //             segs (tid&3)*4 + it, it<4.
    const int lrA   = tid >> 2;
    const int lsgA0 = (tid & 3) * 4;
    // B cp.async: 256 rows x 16 segs = 4096; row tid>>1, segs (tid&1)*8+it, it<8.
    const int lrB   = tid >> 1;
    const int lsgB0 = (tid & 1) * 8;

    auto issue = [&](int chunk) {
        const int k0  = chunk * 128;
        const int buf = chunk & 1;
        {   // A
            const uint32_t base = smb + (uint32_t)(buf * S1_AMAT) * 2;
            const size_t src0 = ((size_t)n * BT + row0 + lrA) * D + k0;
            const uint32_t d0 = base + (uint32_t)(lrA * LDA2) * 2;
            #pragma unroll
            for (int it = 0; it < 4; it++) {
                const int seg = lsgA0 + it;
                cp16(d0 + seg * 16, g_x16 + src0 + seg * 8);
            }
        }
        {   // B
            const uint32_t base =
                smb + (uint32_t)(S1_BBASE + buf * S1_BMAT) * 2;
            const int c = lrB;                       // 0..255
            const int e = (c < 128) ? (ja + c) : (512 + ja + (c - 128));
            const size_t src0 = ((size_t)n * E2 + e) * D + k0;
            const uint32_t d0 = base + (uint32_t)(c * LDA2) * 2;
            #pragma unroll
            for (int it = 0; it < 8; it++) {
                const int seg = lsgB0 + it;
                cp16(d0 + seg * 16, g_w16 + src0 + seg * 8);
            }
        }
        cp_commit();
    };

    issue(0);

    for (int chunk = 0; chunk < 4; chunk++) {
        cp_wait0();
        __syncthreads();

        if (chunk + 1 < 4) issue(chunk + 1);

        const int buf = chunk & 1;
        const uint32_t sA = smb + (uint32_t)(buf * S1_AMAT) * 2;
        const uint32_t sB = smb + (uint32_t)(S1_BBASE + buf * S1_BMAT) * 2;

        #pragma unroll
        for (int ks = 0; ks < 8; ks++) {
            uint32_t ah[2][4];
            #pragma unroll
            for (int mi = 0; mi < 2; mi++) {
                const uint32_t off =
                    (uint32_t)(((aRow + mi * 16) * LDA2 + ks * 16 + aK) * 2);
                ldm_x4(ah[mi], sA + off);
            }
            #pragma unroll
            for (int idx = 0; idx < 4; idx++) {
                const int bc = (idx < 2) ? (warp_n * 32 + idx * 16)
                                         : (128 + warp_n * 32 + (idx - 2) * 16);
                const uint32_t off =
                    (uint32_t)(((bc + bN) * LDA2 + ks * 16 + bK) * 2);
                uint32_t bh[4];
                ldm_x4(bh, sB + off);
                #pragma unroll
                for (int s = 0; s < 2; s++) {
                    #pragma unroll
                    for (int mi = 0; mi < 2; mi++)
                        mma_f16(acc[mi][idx * 2 + s], ah[mi], &bh[2 * s]);
                }
            }
        }
    }

    // ---- Epilogue: bias + GLU, write h as f16 (band-major) ----
    const int g   = lane >> 2;
    const int tig = lane & 3;

    #pragma unroll
    for (int mi = 0; mi < 2; mi++) {
        #pragma unroll
        for (int j = 0; j < 4; j++) {
            const int col = ja + warp_n * 32 + j * 8 + 2 * tig;
            const float ba0 = b0[n * E2 + col];
            const float ba1 = b0[n * E2 + col + 1];
            const float bg0 = b0[n * E2 + 512 + col];
            const float bg1 = b0[n * E2 + 512 + col + 1];
            #pragma unroll
            for (int half = 0; half < 2; half++) {
                const int row = row0 + warp_m * 32 + mi * 16 + g + half * 8;
                const float a0 = acc[mi][j][half * 2 + 0] + ba0;
                const float a1 = acc[mi][j][half * 2 + 1] + ba1;
                const float q0 = acc[mi][j + 4][half * 2 + 0] + bg0;
                const float q1 = acc[mi][j + 4][half * 2 + 1] + bg1;
                const size_t o = ((size_t)n * BT + row) * D + col;
                *(uint32_t*)(g_h16 + o) = pack_h2(glu(a0, q0), glu(a1, q1));
            }
        }
    }
}

// ---------------------------------------------------------------------------
// Stage 2 (fp16, R13 shape): out = GLU(h[:,n,:] @ W1_slice + b1_slice)
// Grid: (16, 8, 24); blocks past di exit. Block 256 (8 warps: 4 m x 2 n),
// 2 CTAs/SM. K chunk 64; A: 3 stages, B: 2 stages.
// ---------------------------------------------------------------------------
#define S2_AMAT   (128 * LDA)               // 9216
#define S2_BMAT   (64 * LDA)                // 4608
#define S2_BBASE  (3 * S2_AMAT)
#define S2_SMEM   ((3 * S2_AMAT + 2 * S2_BMAT) * 2)   // 73728 B

__global__ __launch_bounds__(256, 2) void stage2_mma_kernel(
    const float* __restrict__ b1, float* __restrict__ out)
{
    const int n   = blockIdx.z;
    const int gl  = n >> 2;
    const int di  = 8 << gl;
    const int jd0 = blockIdx.y * 32;
    if (jd0 >= di) return;

    const int on   = 32 * ((1 << gl) - 1) + (n & 3) * di;
    const int coff = 2 * on;
    const int row0 = blockIdx.x * 128;

    extern __shared__ __half smem2[];

    const int tid = threadIdx.x;
    const int wid = tid >> 5;
    const int lane = tid & 31;
    const int warp_m = wid & 3;
    const int warp_n = wid >> 2;

    float acc[2][4][4];
    #pragma unroll
    for (int mi = 0; mi < 2; mi++)
        #pragma unroll
        for (int j = 0; j < 4; j++)
            #pragma unroll
            for (int r = 0; r < 4; r++) acc[mi][j][r] = 0.0f;

    const uint32_t smb = smem_u32(smem2);

    const int aRow = warp_m * 32 + (lane & 15);
    const int aK   = (lane >> 4) * 8;
    const int bN   = (lane & 7) + ((lane >> 4) << 3);
    const int bK   = ((lane >> 3) & 1) << 3;

    const int lrA   = tid >> 1;
    const int lsgA0 = (tid & 1) * 4;
    const int lrB   = tid >> 2;
    const int lsgB0 = (tid & 3) * 2;

    const int jdB   = jd0 + (lrB & 31);
    const bool valB = jdB < di;
    const int eB    = (lrB < 32) ? (coff + jdB) : (coff + di + jdB);

    auto issueA = [&](int chunk) {
        const int k0 = chunk * 64;
        const uint32_t base = smb + (uint32_t)((chunk % 3) * S2_AMAT) * 2;
        const size_t src0 = ((size_t)n * BT + row0 + lrA) * D + k0;
        #pragma unroll
        for (int it = 0; it < 4; it++) {
            const int seg = lsgA0 + it;
            cp16(base + (uint32_t)(lrA * LDA + seg * 8) * 2,
                 g_h16 + src0 + seg * 8);
        }
        cp_commit();
    };
    auto issueB = [&](int chunk) {
        const int k0 = chunk * 64;
        const uint32_t base =
            smb + (uint32_t)(S2_BBASE + (chunk & 1) * S2_BMAT) * 2;
        const size_t src0 = (size_t)eB * D + k0;
        #pragma unroll
        for (int it = 0; it < 2; it++) {
            const int seg = lsgB0 + it;
            cp16z(base + (uint32_t)(lrB * LDA + seg * 8) * 2,
                  g_v16 + src0 + seg * 8, valB);
        }
        cp_commit();
    };

    issueA(0);
    issueB(0);
    issueA(1);

    for (int chunk = 0; chunk < 8; chunk++) {
        if (chunk < 7) cp_wait1();
        else           cp_wait0();
        __syncthreads();

        if (chunk + 1 < 8) issueB(chunk + 1);
        if (chunk + 2 < 8) issueA(chunk + 2);

        const uint32_t sA = smb + (uint32_t)((chunk % 3) * S2_AMAT) * 2;
        const uint32_t sB =
            smb + (uint32_t)(S2_BBASE + (chunk & 1) * S2_BMAT) * 2;

        #pragma unroll
        for (int ks = 0; ks < 4; ks++) {
            uint32_t ah[2][4];
            #pragma unroll
            for (int mi = 0; mi < 2; mi++) {
                const uint32_t off =
                    (uint32_t)(((aRow + mi * 16) * LDA + ks * 16 + aK) * 2);
                ldm_x4(ah[mi], sA + off);
            }
            #pragma unroll
            for (int idx = 0; idx < 2; idx++) {
                const int bc = (idx == 0) ? (warp_n * 16) : (32 + warp_n * 16);
                const uint32_t off =
                    (uint32_t)(((bc + bN) * LDA + ks * 16 + bK) * 2);
                uint32_t bh[4];
                ldm_x4(bh, sB + off);
                #pragma unroll
                for (int s = 0; s < 2; s++) {
                    #pragma unroll
                    for (int mi = 0; mi < 2; mi++)
                        mma_f16(acc[mi][idx * 2 + s], ah[mi], &bh[2 * s]);
                }
            }
        }
    }

    // ---- Epilogue ----
    const int g   = lane >> 2;
    const int tig = lane & 3;

    #pragma unroll
    for (int mi = 0; mi < 2; mi++) {
        #pragma unroll
        for (int j = 0; j < 2; j++) {
            const int jd = jd0 + warp_n * 16 + j * 8 + 2 * tig;
            if (jd >= di) continue;
            const float ba0 = b1[coff + jd];
            const float ba1 = b1[coff + jd + 1];
            const float bg0 = b1[coff + di + jd];
            const float bg1 = b1[coff + di + jd + 1];
            #pragma unroll
            for (int half = 0; half < 2; half++) {
                const int row = row0 + warp_m * 32 + mi * 16 + g + half * 8;
                const float a0 = acc[mi][j][half * 2 + 0] + ba0;
                const float a1 = acc[mi][j][half * 2 + 1] + ba1;
                const float q0 = acc[mi][j + 2][half * 2 + 0] + bg0;
                const float q1 = acc[mi][j + 2][half * 2 + 1] + bg1;
                float2 ov;
                ov.x = glu(a0, q0);
                ov.y = glu(a1, q1);
                *(float2*)&out[(size_t)row * OUTW + on + jd] = ov;
            }
        }
    }
}

// ---------------------------------------------------------------------------
extern "C" void kernel_launch(void* const* d_in, const int* in_sizes, int n_in,
                              void* d_out, int out_size)
{
    const float* x  = (const float*)d_in[0];
    const float* W0 = (const float*)d_in[1];
    const float* b0 = (const float*)d_in[2];
    const float* W1 = (const float*)d_in[3];
    const float* b1 = (const float*)d_in[4];
    float* out = (float*)d_out;

    cudaFuncSetAttribute(stage1_mma_kernel,
                         cudaFuncAttributeMaxDynamicSharedMemorySize, S1_SMEM);
    cudaFuncSetAttribute(stage2_mma_kernel,
                         cudaFuncAttributeMaxDynamicSharedMemorySize, S2_SMEM);

    cvt_x16_kernel<<<4096, 256>>>(x);
    cvt_w0_kernel<<<dim3(D / 32, E2 / 32, NB), dim3(32, 8)>>>(W0);
    cvt_w1_kernel<<<dim3(D / 32, W1C / 32, 1), dim3(32, 8)>>>(W1);
    stage1_mma_kernel<<<dim3(BT / 128, 4, NB), 512, S1_SMEM>>>(b0);
    stage2_mma_kernel<<<dim3(BT / 128, 8, NB), 256, S2_SMEM>>>(b1, out);
}

// round 16
// speedup vs baseline: 1.2004x; 1.2004x over previous
#include <cuda_runtime.h>
#include <cuda_bf16.h>
#include <cuda_fp16.h>
#include <cstdint>

// ---------------------------------------------------------------------------
// Problem constants
// ---------------------------------------------------------------------------
#define BT    2048      // B*T
#define NB    24        // bands
#define D     512       // DIM
#define E2    1024      // 2*DIM
#define OUTW  2016      // sum(DIM_INPUTS)
#define W1C   4032      // 2*OUTW
#define LDA   72        // smem row stride (64 data + 8 pad) f16

// Scratch globals (all f16). x and h are BAND-MAJOR: [n][row][k].
__device__ __half g_x16[(size_t)NB * BT * D];  // x    f16 [n][row][k]
__device__ __half g_w16[(size_t)NB * E2 * D];  // W0^T f16 [n][e][k]
__device__ __half g_h16[(size_t)NB * BT * D];  // h    f16 [n][row][k]
__device__ __half g_v16[(size_t)W1C * D];      // W1^T f16 [e][k]

// ---------------------------------------------------------------------------
// Helpers
// ---------------------------------------------------------------------------
__device__ __forceinline__ uint32_t smem_u32(const void* p) {
    uint32_t a;
    asm("{ .reg .u64 t; cvta.to.shared.u64 t, %1; cvt.u32.u64 %0, t; }"
        : "=r"(a) : "l"(p));
    return a;
}
__device__ __forceinline__ void cp16(uint32_t dst, const void* src) {
    asm volatile("cp.async.cg.shared.global [%0], [%1], 16;"
                 :: "r"(dst), "l"(src));
}
__device__ __forceinline__ void cp16z(uint32_t dst, const void* src, bool valid) {
    int sz = valid ? 16 : 0;
    asm volatile("cp.async.cg.shared.global [%0], [%1], 16, %2;"
                 :: "r"(dst), "l"(src), "r"(sz));
}
__device__ __forceinline__ void cp_commit() {
    asm volatile("cp.async.commit_group;");
}
__device__ __forceinline__ void cp_wait1() {
    asm volatile("cp.async.wait_group 1;");
}
__device__ __forceinline__ void cp_wait0() {
    asm volatile("cp.async.wait_group 0;");
}
__device__ __forceinline__ void ldm_x4(uint32_t* r, uint32_t addr) {
    asm volatile("ldmatrix.sync.aligned.m8n8.x4.shared.b16 {%0,%1,%2,%3}, [%4];"
        : "=r"(r[0]), "=r"(r[1]), "=r"(r[2]), "=r"(r[3]) : "r"(addr));
}
__device__ __forceinline__ void mma_f16(float* c, const uint32_t* a,
                                        const uint32_t* b) {
    asm volatile(
        "mma.sync.aligned.m16n8k16.row.col.f32.f16.f16.f32 "
        "{%0,%1,%2,%3}, {%4,%5,%6,%7}, {%8,%9}, {%0,%1,%2,%3};"
        : "+f"(c[0]), "+f"(c[1]), "+f"(c[2]), "+f"(c[3])
        : "r"(a[0]), "r"(a[1]), "r"(a[2]), "r"(a[3]), "r"(b[0]), "r"(b[1]));
}
__device__ __forceinline__ float fast_tanh(float x) {
    float r; asm("tanh.approx.f32 %0, %1;" : "=f"(r) : "f"(x)); return r;
}
__device__ __forceinline__ float glu(float a, float g) {
    return fast_tanh(a) * __fdividef(1.0f, 1.0f + __expf(-g));
}
__device__ __forceinline__ uint32_t pack_h2(float lo, float hi) {
    __half2 t = __floats2half2_rn(lo, hi);
    return *(uint32_t*)&t;
}

// ---------------------------------------------------------------------------
// Fused prologue: one kernel, flat block dispatch.
//   blocks [0, 12288)          : W0 transpose tiles (16 k x 32 e x 24 n)
//   blocks [12288, 14304)      : W1 transpose tiles (16 k x 126 e)
//   blocks [14304, 17376)      : x f32 -> f16 band-major, grid-stride
// Bandwidth-bound x blocks overlap latency-bound transpose blocks; two
// launch/tail boundaries removed vs three separate kernels.
// ---------------------------------------------------------------------------
#define NW0_BLK   (16 * 32 * NB)       // 12288
#define NW1_BLK   (16 * (W1C / 32))    // 2016
#define NX_BLK    3072
#define NCVT_BLK  (NW0_BLK + NW1_BLK + NX_BLK)

__global__ __launch_bounds__(256) void cvt_all_kernel(
    const float* __restrict__ x, const float* __restrict__ W0,
    const float* __restrict__ W1)
{
    __shared__ float t[32][33];
    const int bid = blockIdx.x;
    const int tid = threadIdx.x;
    const int tx  = tid & 31;
    const int ty  = tid >> 5;      // 0..7

    if (bid < NW0_BLK) {
        // ---- W0 [n][k][e] -> g_w16 [n][e][k] ----
        const int k0   = (bid & 15) * 32;
        const int rest = bid >> 4;
        const int e0   = (rest & 31) * 32;
        const int n    = rest >> 5;

        #pragma unroll
        for (int i = 0; i < 32; i += 8)
            t[ty + i][tx] = W0[((size_t)n * D + k0 + ty + i) * E2 + e0 + tx];
        __syncthreads();
        #pragma unroll
        for (int i = 0; i < 32; i += 8) {
            float v = t[tx][ty + i];
            g_w16[((size_t)n * E2 + e0 + ty + i) * D + k0 + tx] =
                __float2half_rn(v);
        }
    } else if (bid < NW0_BLK + NW1_BLK) {
        // ---- W1 [k][e] -> g_v16 [e][k] ----
        const int b  = bid - NW0_BLK;
        const int k0 = (b & 15) * 32;
        const int e0 = (b >> 4) * 32;

        #pragma unroll
        for (int i = 0; i < 32; i += 8)
            t[ty + i][tx] = W1[(size_t)(k0 + ty + i) * W1C + e0 + tx];
        __syncthreads();
        #pragma unroll
        for (int i = 0; i < 32; i += 8) {
            float v = t[tx][ty + i];
            g_v16[(size_t)(e0 + ty + i) * D + k0 + tx] = __float2half_rn(v);
        }
    } else {
        // ---- x f32 [row][n][k] -> g_x16 f16 [n][row][k], grid-stride ----
        const int b = bid - (NW0_BLK + NW1_BLK);
        const size_t total8 = (size_t)BT * NB * D / 8;
        const float4* in = (const float4*)x;
        for (size_t i = (size_t)b * 256 + tid; i < total8;
             i += (size_t)NX_BLK * 256) {
            const size_t e0  = i * 8;
            const int    row = (int)(e0 / (NB * D));
            const int    rem = (int)(e0 % (NB * D));
            const int    n   = rem / D;
            const int    k   = rem % D;

            float4 v0 = in[2 * i];
            float4 v1 = in[2 * i + 1];
            uint4 o;
            o.x = pack_h2(v0.x, v0.y);
            o.y = pack_h2(v0.z, v0.w);
            o.z = pack_h2(v1.x, v1.y);
            o.w = pack_h2(v1.z, v1.w);
            *(uint4*)(g_x16 + ((size_t)n * BT + row) * D + k) = o;
        }
    }
}

// ---------------------------------------------------------------------------
// Stage 1 (fp16, R13 shape): z = x @ W0[n] + b0[n]; h = GLU(z) -> f16
// Grid: (16, 8, 24). Block 256 (8 warps: 4 m x 2 n), 2 CTAs/SM.
// K chunked at 64 (8 chunks); A: 3 stages, B: 2 stages, one sync per chunk.
// ---------------------------------------------------------------------------
#define S1_MAT    (128 * LDA)               // 9216 elems per matrix stage
#define S1_BBASE  (3 * S1_MAT)              // A stages 0..2
#define S1_SMEM   (5 * S1_MAT * 2)          // 92160 B

__global__ __launch_bounds__(256, 2) void stage1_mma_kernel(
    const float* __restrict__ b0)
{
    extern __shared__ __half smem[];

    const int tid = threadIdx.x;
    const int wid = tid >> 5;
    const int lane = tid & 31;
    const int warp_m = wid & 3;
    const int warp_n = wid >> 2;
    const int row0 = blockIdx.x * 128;
    const int ja   = blockIdx.y * 64;
    const int n    = blockIdx.z;

    float acc[2][8][4];
    #pragma unroll
    for (int mi = 0; mi < 2; mi++)
        #pragma unroll
        for (int j = 0; j < 8; j++)
            #pragma unroll
            for (int r = 0; r < 4; r++) acc[mi][j][r] = 0.0f;

    const uint32_t smb = smem_u32(smem);

    const int aRow = warp_m * 32 + (lane & 15);
    const int aK   = (lane >> 4) * 8;
    const int bN   = (lane & 7) + ((lane >> 4) << 3);
    const int bK   = ((lane >> 3) & 1) << 3;

    const int lr   = tid >> 1;             // 0..127
    const int lsg0 = (tid & 1) * 4;        // seg base

    auto issueA = [&](int chunk) {
        const int k0 = chunk * 64;
        const uint32_t base = smb + (uint32_t)((chunk % 3) * S1_MAT) * 2;
        const size_t src0 = ((size_t)n * BT + row0 + lr) * D + k0;
        #pragma unroll
        for (int it = 0; it < 4; it++) {
            const int seg = lsg0 + it;
            cp16(base + (uint32_t)(lr * LDA + seg * 8) * 2,
                 g_x16 + src0 + seg * 8);
        }
        cp_commit();
    };
    auto issueB = [&](int chunk) {
        const int k0 = chunk * 64;
        const uint32_t base =
            smb + (uint32_t)(S1_BBASE + (chunk & 1) * S1_MAT) * 2;
        const int c = lr;
        const int e = (c < 64) ? (ja + c) : (512 + ja + (c - 64));
        const size_t src0 = ((size_t)n * E2 + e) * D + k0;
        #pragma unroll
        for (int it = 0; it < 4; it++) {
            const int seg = lsg0 + it;
            cp16(base + (uint32_t)(c * LDA + seg * 8) * 2,
                 g_w16 + src0 + seg * 8);
        }
        cp_commit();
    };

    issueA(0);
    issueB(0);
    issueA(1);

    for (int chunk = 0; chunk < 8; chunk++) {
        if (chunk < 7) cp_wait1();
        else           cp_wait0();
        __syncthreads();

        if (chunk + 1 < 8) issueB(chunk + 1);
        if (chunk + 2 < 8) issueA(chunk + 2);

        const uint32_t sA = smb + (uint32_t)((chunk % 3) * S1_MAT) * 2;
        const uint32_t sB =
            smb + (uint32_t)(S1_BBASE + (chunk & 1) * S1_MAT) * 2;

        #pragma unroll
        for (int ks = 0; ks < 4; ks++) {
            uint32_t ah[2][4];
            #pragma unroll
            for (int mi = 0; mi < 2; mi++) {
                const uint32_t off =
                    (uint32_t)(((aRow + mi * 16) * LDA + ks * 16 + aK) * 2);
                ldm_x4(ah[mi], sA + off);
            }
            #pragma unroll
            for (int idx = 0; idx < 4; idx++) {
                const int bc = (idx < 2) ? (warp_n * 32 + idx * 16)
                                         : (64 + warp_n * 32 + (idx - 2) * 16);
                const uint32_t off =
                    (uint32_t)(((bc + bN) * LDA + ks * 16 + bK) * 2);
                uint32_t bh[4];
                ldm_x4(bh, sB + off);
                #pragma unroll
                for (int s = 0; s < 2; s++) {
                    #pragma unroll
                    for (int mi = 0; mi < 2; mi++)
                        mma_f16(acc[mi][idx * 2 + s], ah[mi], &bh[2 * s]);
                }
            }
        }
    }

    // ---- Epilogue: bias + GLU, write h as f16 (band-major) ----
    const int g   = lane >> 2;
    const int tig = lane & 3;

    #pragma unroll
    for (int mi = 0; mi < 2; mi++) {
        #pragma unroll
        for (int j = 0; j < 4; j++) {
            const int col = ja + warp_n * 32 + j * 8 + 2 * tig;
            const float ba0 = b0[n * E2 + col];
            const float ba1 = b0[n * E2 + col + 1];
            const float bg0 = b0[n * E2 + 512 + col];
            const float bg1 = b0[n * E2 + 512 + col + 1];
            #pragma unroll
            for (int half = 0; half < 2; half++) {
                const int row = row0 + warp_m * 32 + mi * 16 + g + half * 8;
                const float a0 = acc[mi][j][half * 2 + 0] + ba0;
                const float a1 = acc[mi][j][half * 2 + 1] + ba1;
                const float q0 = acc[mi][j + 4][half * 2 + 0] + bg0;
                const float q1 = acc[mi][j + 4][half * 2 + 1] + bg1;
                const size_t o = ((size_t)n * BT + row) * D + col;
                *(uint32_t*)(g_h16 + o) = pack_h2(glu(a0, q0), glu(a1, q1));
            }
        }
    }
}

// ---------------------------------------------------------------------------
// Stage 2 (fp16, R13 shape): out = GLU(h[:,n,:] @ W1_slice + b1_slice)
// Grid: (16, 8, 24); blocks past di exit. Block 256 (8 warps: 4 m x 2 n),
// 2 CTAs/SM. K chunk 64; A: 3 stages, B: 2 stages.
// ---------------------------------------------------------------------------
#define S2_AMAT   (128 * LDA)               // 9216
#define S2_BMAT   (64 * LDA)                // 4608
#define S2_BBASE  (3 * S2_AMAT)
#define S2_SMEM   ((3 * S2_AMAT + 2 * S2_BMAT) * 2)   // 73728 B

__global__ __launch_bounds__(256, 2) void stage2_mma_kernel(
    const float* __restrict__ b1, float* __restrict__ out)
{
    const int n   = blockIdx.z;
    const int gl  = n >> 2;
    const int di  = 8 << gl;
    const int jd0 = blockIdx.y * 32;
    if (jd0 >= di) return;

    const int on   = 32 * ((1 << gl) - 1) + (n & 3) * di;
    const int coff = 2 * on;
    const int row0 = blockIdx.x * 128;

    extern __shared__ __half smem2[];

    const int tid = threadIdx.x;
    const int wid = tid >> 5;
    const int lane = tid & 31;
    const int warp_m = wid & 3;
    const int warp_n = wid >> 2;

    float acc[2][4][4];
    #pragma unroll
    for (int mi = 0; mi < 2; mi++)
        #pragma unroll
        for (int j = 0; j < 4; j++)
            #pragma unroll
            for (int r = 0; r < 4; r++) acc[mi][j][r] = 0.0f;

    const uint32_t smb = smem_u32(smem2);

    const int aRow = warp_m * 32 + (lane & 15);
    const int aK   = (lane >> 4) * 8;
    const int bN   = (lane & 7) + ((lane >> 4) << 3);
    const int bK   = ((lane >> 3) & 1) << 3;

    const int lrA   = tid >> 1;
    const int lsgA0 = (tid & 1) * 4;
    const int lrB   = tid >> 2;
    const int lsgB0 = (tid & 3) * 2;

    const int jdB   = jd0 + (lrB & 31);
    const bool valB = jdB < di;
    const int eB    = (lrB < 32) ? (coff + jdB) : (coff + di + jdB);

    auto issueA = [&](int chunk) {
        const int k0 = chunk * 64;
        const uint32_t base = smb + (uint32_t)((chunk % 3) * S2_AMAT) * 2;
        const size_t src0 = ((size_t)n * BT + row0 + lrA) * D + k0;
        #pragma unroll
        for (int it = 0; it < 4; it++) {
            const int seg = lsgA0 + it;
            cp16(base + (uint32_t)(lrA * LDA + seg * 8) * 2,
                 g_h16 + src0 + seg * 8);
        }
        cp_commit();
    };
    auto issueB = [&](int chunk) {
        const int k0 = chunk * 64;
        const uint32_t base =
            smb + (uint32_t)(S2_BBASE + (chunk & 1) * S2_BMAT) * 2;
        const size_t src0 = (size_t)eB * D + k0;
        #pragma unroll
        for (int it = 0; it < 2; it++) {
            const int seg = lsgB0 + it;
            cp16z(base + (uint32_t)(lrB * LDA + seg * 8) * 2,
                  g_v16 + src0 + seg * 8, valB);
        }
        cp_commit();
    };

    issueA(0);
    issueB(0);
    issueA(1);

    for (int chunk = 0; chunk < 8; chunk++) {
        if (chunk < 7) cp_wait1();
        else           cp_wait0();
        __syncthreads();

        if (chunk + 1 < 8) issueB(chunk + 1);
        if (chunk + 2 < 8) issueA(chunk + 2);

        const uint32_t sA = smb + (uint32_t)((chunk % 3) * S2_AMAT) * 2;
        const uint32_t sB =
            smb + (uint32_t)(S2_BBASE + (chunk & 1) * S2_BMAT) * 2;

        #pragma unroll
        for (int ks = 0; ks < 4; ks++) {
            uint32_t ah[2][4];
            #pragma unroll
            for (int mi = 0; mi < 2; mi++) {
                const uint32_t off =
                    (uint32_t)(((aRow + mi * 16) * LDA + ks * 16 + aK) * 2);
                ldm_x4(ah[mi], sA + off);
            }
            #pragma unroll
            for (int idx = 0; idx < 2; idx++) {
                const int bc = (idx == 0) ? (warp_n * 16) : (32 + warp_n * 16);
                const uint32_t off =
                    (uint32_t)(((bc + bN) * LDA + ks * 16 + bK) * 2);
                uint32_t bh[4];
                ldm_x4(bh, sB + off);
                #pragma unroll
                for (int s = 0; s < 2; s++) {
                    #pragma unroll
                    for (int mi = 0; mi < 2; mi++)
                        mma_f16(acc[mi][idx * 2 + s], ah[mi], &bh[2 * s]);
                }
            }
        }
    }

    // ---- Epilogue ----
    const int g   = lane >> 2;
    const int tig = lane & 3;

    #pragma unroll
    for (int mi = 0; mi < 2; mi++) {
        #pragma unroll
        for (int j = 0; j < 2; j++) {
            const int jd = jd0 + warp_n * 16 + j * 8 + 2 * tig;
            if (jd >= di) continue;
            const float ba0 = b1[coff + jd];
            const float ba1 = b1[coff + jd + 1];
            const float bg0 = b1[coff + di + jd];
            const float bg1 = b1[coff + di + jd + 1];
            #pragma unroll
            for (int half = 0; half < 2; half++) {
                const int row = row0 + warp_m * 32 + mi * 16 + g + half * 8;
                const float a0 = acc[mi][j][half * 2 + 0] + ba0;
                const float a1 = acc[mi][j][half * 2 + 1] + ba1;
                const float q0 = acc[mi][j + 2][half * 2 + 0] + bg0;
                const float q1 = acc[mi][j + 2][half * 2 + 1] + bg1;
                float2 ov;
                ov.x = glu(a0, q0);
                ov.y = glu(a1, q1);
                *(float2*)&out[(size_t)row * OUTW + on + jd] = ov;
            }
        }
    }
}

// ---------------------------------------------------------------------------
extern "C" void kernel_launch(void* const* d_in, const int* in_sizes, int n_in,
                              void* d_out, int out_size)
{
    const float* x  = (const float*)d_in[0];
    const float* W0 = (const float*)d_in[1];
    const float* b0 = (const float*)d_in[2];
    const float* W1 = (const float*)d_in[3];
    const float* b1 = (const float*)d_in[4];
    float* out = (float*)d_out;

    cudaFuncSetAttribute(stage1_mma_kernel,
                         cudaFuncAttributeMaxDynamicSharedMemorySize, S1_SMEM);
    cudaFuncSetAttribute(stage2_mma_kernel,
                         cudaFuncAttributeMaxDynamicSharedMemorySize, S2_SMEM);

    cvt_all_kernel<<<NCVT_BLK, 256>>>(x, W0, W1);
    stage1_mma_kernel<<<dim3(BT / 128, 8, NB), 256, S1_SMEM>>>(b0);
    stage2_mma_kernel<<<dim3(BT / 128, 8, NB), 256, S2_SMEM>>>(b1, out);
}